// round 16
// baseline (speedup 1.0000x reference)
#include <cuda_runtime.h>
#include <cuda_fp16.h>
#include <cstdint>

#define VOCAB 32000
#define EDIM  1024
#define HDIM  1024
#define NLAY  2
#define BSZ   64
#define TST   64
#define GDIM  4096
#define START_TOK 1

#define RS 72                         /* smem row stride in fp16 elems */
#define A_LIMB (64*RS)
#define B_LIMB (256*RS)
#define STAGE_ELE (2*A_LIMB + 2*B_LIMB)      /* 46080 fp16 */
#define SMEM_SZ (2*STAGE_ELE*2)              /* 184320 B, 2 stages */
#define SCL 1024.0f
#define SCI (1.0f/(1024.0f*1024.0f))
#define CAP 512                       /* candidate list capacity */

// ---------------- device globals (no allocation allowed) -------------------
__device__ __half d_wih_s[2][NLAY*GDIM*HDIM];
__device__ __half d_whh_s[2][NLAY*GDIM*HDIM];
__device__ __half d_o2w_s[2][EDIM*HDIM];
__device__ __half d_sw0[VOCAB*EDIM];         /* score weights: high limb only */
__device__ float  g_bn0[VOCAB], g_bn1[VOCAB];/* per-row limb norms (scaled) */
__device__ __half d_xs[2][64*HDIM];
__device__ __half d_hs[NLAY][2][64*HDIM];
__device__ __half d_hid_s[2][64*HDIM];
__device__ float  g_hid32[BSZ][EDIM];        /* fp32 hid for exact refinement */
__device__ float g_part[8][BSZ][GDIM];
__device__ float e_part[8][BSZ][EDIM];
__device__ float g_c[NLAY][BSZ][HDIM];
__device__ int   g_tok[BSZ];

// fp16 warp MMA: D(16x8,f32) += A(16x16,row) * B(16x8,col)  [sm_80+, plain]
#define MMA_F16(d, a, b)                                                      \
  asm volatile("mma.sync.aligned.m16n8k16.row.col.f32.f16.f16.f32 "           \
    "{%0,%1,%2,%3},{%4,%5,%6,%7},{%8,%9},{%0,%1,%2,%3};"                      \
    : "+f"((d)[0]), "+f"((d)[1]), "+f"((d)[2]), "+f"((d)[3])                  \
    : "r"((a)[0]), "r"((a)[1]), "r"((a)[2]), "r"((a)[3]),                     \
      "r"((b)[0]), "r"((b)[1]))

#define LDSM_X4(r0,r1,r2,r3, ad)                                              \
  asm volatile("ldmatrix.sync.aligned.m8n8.x4.shared.b16 {%0,%1,%2,%3}, [%4];"\
    : "=r"(r0), "=r"(r1), "=r"(r2), "=r"(r3) : "r"(ad))
#define LDSM_X2(r0,r1, ad)                                                    \
  asm volatile("ldmatrix.sync.aligned.m8n8.x2.shared.b16 {%0,%1}, [%2];"      \
    : "=r"(r0), "=r"(r1) : "r"(ad))

#define CP_A16(dst, src)                                                      \
  asm volatile("cp.async.cg.shared.global [%0], [%1], 16;"                    \
    :: "r"(dst), "l"(src) : "memory")
#define CP_COMMIT() asm volatile("cp.async.commit_group;" ::: "memory")
#define CP_WAIT0()  asm volatile("cp.async.wait_group 0;" ::: "memory")
#define CP_WAIT1()  asm volatile("cp.async.wait_group 1;" ::: "memory")

__device__ __forceinline__ uint32_t smem_u32(const void* p) {
  uint32_t a;
  asm("{ .reg .u64 t; cvta.to.shared.u64 t, %1; cvt.u32.u64 %0, t; }" : "=r"(a) : "l"(p));
  return a;
}
// fp32 -> 2 fp16 limbs, pre-scaled by 2^10 (residual ~2^-22 relative)
__device__ __forceinline__ void split2(float x, __half& h0, __half& h1) {
  float s = x * SCL;
  h0 = __float2half_rn(s);
  h1 = __float2half_rn(s - __half2float(h0));
}
__device__ __forceinline__ const __half* getA(int s, int l) {
  switch (s) { case 0: return d_xs[l]; case 1: return d_hs[0][l];
               case 2: return d_hs[1][l]; default: return d_hid_s[l]; }
}
__device__ __forceinline__ const __half* getB(int s, int l) {
  switch (s) {
    case 0: return d_wih_s[l];
    case 1: return d_whh_s[l];
    case 2: return d_wih_s[l] + (size_t)GDIM * HDIM;
    case 3: return d_whh_s[l] + (size_t)GDIM * HDIM;
    case 4: return d_o2w_s[l];
    default: return d_sw0;                   /* limb0 only; l=1 never read */
  }
}

// ---------------- setup kernels ----------------
__global__ void k_init() {
  int i = blockIdx.x * blockDim.x + threadIdx.x;
  if (i < 2 * 64 * HDIM)        (&d_xs[0][0])[i]    = __float2half(0.f);
  if (i < NLAY * 2 * 64 * HDIM) (&d_hs[0][0][0])[i] = __float2half(0.f);
  if (i < 2 * 64 * HDIM)        (&d_hid_s[0][0])[i] = __float2half(0.f);
  if (i < NLAY * BSZ * HDIM)    (&g_c[0][0][0])[i]  = 0.f;
  if (i < BSZ) g_tok[i] = START_TOK;
}

__global__ void k_embed0(const float* __restrict__ emb) {
  int i = blockIdx.x * blockDim.x + threadIdx.x;
  if (i >= BSZ * EDIM) return;
  int b = i >> 10, e = i & (EDIM - 1);
  __half h0, h1;
  split2(emb[(size_t)g_tok[b] * EDIM + e], h0, h1);
  d_xs[0][b * HDIM + e] = h0; d_xs[1][b * HDIM + e] = h1;
}

__global__ void k_splitw(const float* __restrict__ src, int which, long long n) {
  __half *p0, *p1;
  switch (which) {
    case 0:  p0 = d_wih_s[0]; p1 = d_wih_s[1]; break;
    case 1:  p0 = d_whh_s[0]; p1 = d_whh_s[1]; break;
    default: p0 = d_o2w_s[0]; p1 = d_o2w_s[1]; break;
  }
  long long stride = (long long)gridDim.x * blockDim.x;
  for (long long i = (long long)blockIdx.x * blockDim.x + threadIdx.x; i < n; i += stride) {
    __half h0, h1;
    split2(src[i], h0, h1);
    p0[i] = h0; p1[i] = h1;
  }
}

// score weights: store high limb, accumulate per-row norms of both limbs
__global__ void k_splitsw(const float* __restrict__ sw) {
  int warp = (blockIdx.x * blockDim.x + threadIdx.x) >> 5;
  int lane = threadIdx.x & 31;
  if (warp >= VOCAB) return;
  const float* row = sw + (size_t)warp * EDIM;
  float n0 = 0.f, n1 = 0.f;
  for (int e = lane; e < EDIM; e += 32) {
    __half h0, h1;
    split2(row[e], h0, h1);
    d_sw0[(size_t)warp * EDIM + e] = h0;
    float f0 = __half2float(h0), f1 = __half2float(h1);
    n0 = fmaf(f0, f0, n0); n1 = fmaf(f1, f1, n1);
  }
#pragma unroll
  for (int m = 16; m >= 1; m >>= 1) {
    n0 += __shfl_xor_sync(0xffffffffu, n0, m);
    n1 += __shfl_xor_sync(0xffffffffu, n1, m);
  }
  if (lane == 0) { g_bn0[warp] = sqrtf(n0); g_bn1[warp] = sqrtf(n1); }
}

// ---------------- fp16x2 HMMA GEMM, 256 thr, M64 x N256, 2-stage cp.async --
// mode 0: gates partial -> g_part[y]; 1: o2emb partial -> e_part[y];
// mode 2: score, SINGLE limb pass (a0*b0), bias + store to out.
__global__ __launch_bounds__(256) void k_mm(int a1, int b1, int a2, int b2,
                                            int cpb, int ysplit, int mode,
                                            const float* __restrict__ bias,
                                            float* __restrict__ out, int t) {
  extern __shared__ __half sm[];
  const uint32_t sbase = smem_u32(sm);
  const int tid = threadIdx.x, wid = tid >> 5, lane = tid & 31;
  const int qr = lane >> 2, qc = lane & 3;
  const int wm = wid & 3, wn = wid >> 2;
  const int n0 = blockIdx.x * 256;
  const int y = blockIdx.y;
  const int as = (y < ysplit) ? a1 : a2, bs = (y < ysplit) ? b1 : b2;
  const int kbase = ((y < ysplit) ? y : (y - ysplit)) * cpb * 64;
  const int nlB = (mode == 2) ? 1 : 2;

  const __half* Ap[2]; const __half* Bp[2];
#pragma unroll
  for (int l = 0; l < 2; l++) { Ap[l] = getA(as, l); Bp[l] = getB(bs, l); }

  const int arow = ((lane >> 3) & 1) * 8 + (lane & 7);
  const int akof = ((lane >> 4) & 1) * 8;
  const uint32_t A_pre = (uint32_t)(((wm * 16 + arow) * RS + akof) * 2);
  const int brow = lane & 7;
  const int bkof = ((lane >> 3) & 1) * 8;
  const uint32_t B_pre = (uint32_t)(((wn * 128 + brow) * RS + bkof) * 2);

  float acc[16][4];
#pragma unroll
  for (int i = 0; i < 16; i++)
#pragma unroll
    for (int j = 0; j < 4; j++) acc[i][j] = 0.f;

  auto issue_load = [&](int s, int ch) {
    const int kpos = kbase + ch * 64;
    const uint32_t st = sbase + (uint32_t)(s * STAGE_ELE * 2);
#pragma unroll 2
    for (int i = tid; i < 2 * 512; i += 256) {      // A: 2 limbs x 64r x 64k
      int l = i >> 9, q = i & 511, row = q >> 3, f8 = q & 7;
      CP_A16(st + (uint32_t)((l * A_LIMB + row * RS + f8 * 8) * 2),
             Ap[l] + (size_t)row * 1024 + kpos + f8 * 8);
    }
    for (int i = tid; i < nlB * 2048; i += 256) {   // B: nlB limbs x 256r x 64k
      int l = i >> 11, q = i & 2047, row = q >> 3, f8 = q & 7;
      CP_A16(st + (uint32_t)((2 * A_LIMB + l * B_LIMB + row * RS + f8 * 8) * 2),
             Bp[l] + (size_t)(n0 + row) * 1024 + kpos + f8 * 8);
    }
    CP_COMMIT();
  };

  issue_load(0, 0);

  for (int ch = 0; ch < cpb; ch++) {
    const int cur = ch & 1;
    if (ch + 1 < cpb) { issue_load(cur ^ 1, ch + 1); CP_WAIT1(); }
    else              { CP_WAIT0(); }
    __syncthreads();
    const uint32_t sA = sbase + (uint32_t)(cur * STAGE_ELE * 2);
    const uint32_t sB = sA + (uint32_t)(2 * A_LIMB * 2);

#pragma unroll
    for (int k16 = 0; k16 < 4; k16++) {
      uint32_t afr[2][4];
      const uint32_t ak = sA + A_pre + k16 * 32;
      LDSM_X4(afr[0][0], afr[0][1], afr[0][2], afr[0][3], ak);
      if (mode != 2)
        LDSM_X4(afr[1][0], afr[1][1], afr[1][2], afr[1][3],
                ak + (uint32_t)(A_LIMB * 2));
      const uint32_t bk = sB + B_pre + k16 * 32;
#pragma unroll
      for (int n8 = 0; n8 < 16; n8++) {
        uint32_t bfr[2][2];
        LDSM_X2(bfr[0][0], bfr[0][1], bk + (uint32_t)((n8 * 8 * RS) * 2));
        if (mode != 2)
          LDSM_X2(bfr[1][0], bfr[1][1],
                  bk + (uint32_t)((B_LIMB + n8 * 8 * RS) * 2));
        MMA_F16(acc[n8], afr[0], bfr[0]);        // a0*b0
        if (mode != 2) {
          MMA_F16(acc[n8], afr[0], bfr[1]);      // a0*b1
          MMA_F16(acc[n8], afr[1], bfr[0]);      // a1*b0
        }
      }
    }
    __syncthreads();
  }

  const int r0 = wm * 16 + qr, r1 = r0 + 8;
  if (mode == 2) {
#pragma unroll
    for (int n8 = 0; n8 < 16; n8++) {
      int c = n0 + wn * 128 + n8 * 8 + qc * 2;
      float b0 = bias[c], b1 = bias[c + 1];
      *(float2*)(out + ((size_t)r0 * TST + t) * VOCAB + c) =
          make_float2(acc[n8][0] * SCI + b0, acc[n8][1] * SCI + b1);
      *(float2*)(out + ((size_t)r1 * TST + t) * VOCAB + c) =
          make_float2(acc[n8][2] * SCI + b0, acc[n8][3] * SCI + b1);
    }
  } else {
    float* base = (mode == 0) ? &g_part[y][0][0] : &e_part[y][0][0];
    const int ld = (mode == 0) ? GDIM : EDIM;
#pragma unroll
    for (int n8 = 0; n8 < 16; n8++) {
      int c = n0 + wn * 128 + n8 * 8 + qc * 2;
      *(float2*)(base + (size_t)r0 * ld + c) =
          make_float2(acc[n8][0] * SCI, acc[n8][1] * SCI);
      *(float2*)(base + (size_t)r1 * ld + c) =
          make_float2(acc[n8][2] * SCI, acc[n8][3] * SCI);
    }
  }
}

// reduce 8 gate partials + biases, LSTM cell, emit h limbs + c
__global__ void k_act(const float* __restrict__ bih, const float* __restrict__ bhh,
                      int layer) {
  int i = blockIdx.x * blockDim.x + threadIdx.x;
  if (i >= BSZ * HDIM) return;
  int b = i >> 10, hh = i & (HDIM - 1);
  float gi = bih[hh]            + bhh[hh];
  float gf = bih[HDIM + hh]     + bhh[HDIM + hh];
  float gg = bih[2 * HDIM + hh] + bhh[2 * HDIM + hh];
  float go = bih[3 * HDIM + hh] + bhh[3 * HDIM + hh];
#pragma unroll
  for (int s = 0; s < 8; s++) {
    gi += g_part[s][b][hh];
    gf += g_part[s][b][HDIM + hh];
    gg += g_part[s][b][2 * HDIM + hh];
    go += g_part[s][b][3 * HDIM + hh];
  }
  float si = 1.f / (1.f + expf(-gi));
  float sf = 1.f / (1.f + expf(-gf));
  float so = 1.f / (1.f + expf(-go));
  float cn = sf * g_c[layer][b][hh] + si * tanhf(gg);
  float hn = so * tanhf(cn);
  g_c[layer][b][hh] = cn;
  __half h0, h1;
  split2(hn, h0, h1);
  d_hs[layer][0][b * HDIM + hh] = h0;
  d_hs[layer][1][b * HDIM + hh] = h1;
}

// reduce 8 o2emb partials + bias, ReLU, emit hid limbs + fp32 copy
__global__ void k_hidred(const float* __restrict__ o2b) {
  int i = blockIdx.x * blockDim.x + threadIdx.x;
  if (i >= BSZ * EDIM) return;
  int b = i >> 10, e = i & (EDIM - 1);
  float s = o2b[e];
#pragma unroll
  for (int c = 0; c < 8; c++) s += e_part[c][b][e];
  s = fmaxf(s, 0.f);
  g_hid32[b][e] = s;
  __half h0, h1;
  split2(s, h0, h1);
  d_hid_s[0][b * EDIM + e] = h0;
  d_hid_s[1][b * EDIM + e] = h1;
}

// rigorous-margin candidate scan + exact fp32 refinement + next-token embed
__global__ __launch_bounds__(256) void k_refine(const float* __restrict__ sw,
                                                const float* __restrict__ sb,
                                                const float* __restrict__ emb,
                                                float* __restrict__ out,
                                                int t, int wsamp) {
  __shared__ float red0[8], red1[8];
  __shared__ int   cand[CAP];
  __shared__ int   scount;
  __shared__ float sLmax;
  __shared__ int   stok;
  __shared__ float swv[8]; __shared__ int swi[8];
  const int b = blockIdx.x, tid = threadIdx.x, wid = tid >> 5, lane = tid & 31;
  const float* srow = out + ((size_t)b * TST + t) * VOCAB;

  // ‖a0‖, ‖a1‖ over hid limbs (scaled space)
  float s0 = 0.f, s1 = 0.f;
  for (int e = tid; e < EDIM; e += 256) {
    float a0 = __half2float(d_hid_s[0][b * EDIM + e]);
    float a1 = __half2float(d_hid_s[1][b * EDIM + e]);
    s0 = fmaf(a0, a0, s0); s1 = fmaf(a1, a1, s1);
  }
#pragma unroll
  for (int m = 16; m >= 1; m >>= 1) {
    s0 += __shfl_xor_sync(0xffffffffu, s0, m);
    s1 += __shfl_xor_sync(0xffffffffu, s1, m);
  }
  if (lane == 0) { red0[wid] = s0; red1[wid] = s1; }
  __syncthreads();
  if (tid == 0) {
    float n0 = 0.f, n1 = 0.f;
    for (int w = 0; w < 8; w++) { n0 += red0[w]; n1 += red1[w]; }
    red0[0] = sqrtf(n0); red1[0] = sqrtf(n1);
    scount = 0;
  }
  __syncthreads();
  const float na0 = red0[0], na1 = red1[0];

  // Lmax = max(s~ - margin); margin rigorously bounds |s_true - s~|
  float lmax = -3.0e38f;
  for (int v = tid; v < VOCAB; v += 256) {
    float m = SCI * 1.1f * (na0 * g_bn1[v] + na1 * g_bn0[v] + na1 * g_bn1[v]) + 1e-5f;
    float l = srow[v] - m;
    if (l > lmax) lmax = l;
  }
#pragma unroll
  for (int m = 16; m >= 1; m >>= 1)
    lmax = fmaxf(lmax, __shfl_xor_sync(0xffffffffu, lmax, m));
  if (lane == 0) red0[wid] = lmax;
  __syncthreads();
  if (tid == 0) {
    float L = red0[0];
    for (int w = 1; w < 8; w++) L = fmaxf(L, red0[w]);
    sLmax = L;
  }
  __syncthreads();
  const float Lmax = sLmax;

  // candidates: s~ + margin >= Lmax  (provably contains the true argmax)
  for (int v = tid; v < VOCAB; v += 256) {
    float m = SCI * 1.1f * (na0 * g_bn1[v] + na1 * g_bn0[v] + na1 * g_bn1[v]) + 1e-5f;
    if (srow[v] + m >= Lmax) {
      int idx = atomicAdd(&scount, 1);
      if (idx < CAP) cand[idx] = v;
    }
  }
  __syncthreads();
  const int nc = scount;
  float bv = -3.0e38f; int bi = 0x7fffffff;
  if (nc <= CAP) {
    for (int c = wid; c < nc; c += 8) {              // one warp per candidate
      int v = cand[c];
      float s = 0.f;
      for (int e = lane; e < EDIM; e += 32)
        s = fmaf(g_hid32[b][e], sw[(size_t)v * EDIM + e], s);
#pragma unroll
      for (int m = 16; m >= 1; m >>= 1) s += __shfl_xor_sync(0xffffffffu, s, m);
      s += sb[v];
      if (lane == 0 && (s > bv || (s == bv && v < bi))) { bv = s; bi = v; }
    }
    if (lane == 0) { swv[wid] = bv; swi[wid] = bi; }
  } else {                                           // fallback (never expected)
    for (int v = tid; v < VOCAB; v += 256) {
      float s = 0.f;
      for (int e = 0; e < EDIM; e++)
        s = fmaf(g_hid32[b][e], sw[(size_t)v * EDIM + e], s);
      s += sb[v];
      if (s > bv || (s == bv && v < bi)) { bv = s; bi = v; }
    }
#pragma unroll
    for (int m = 16; m >= 1; m >>= 1) {
      float ov = __shfl_xor_sync(0xffffffffu, bv, m);
      int   oi = __shfl_xor_sync(0xffffffffu, bi, m);
      if (ov > bv || (ov == bv && oi < bi)) { bv = ov; bi = oi; }
    }
    if (lane == 0) { swv[wid] = bv; swi[wid] = bi; }
  }
  __syncthreads();
  if (tid == 0) {
    float fv = swv[0]; int fi = swi[0];
    for (int w = 1; w < 8; w++)
      if (swv[w] > fv || (swv[w] == fv && swi[w] < fi)) { fv = swv[w]; fi = swi[w]; }
    stok = fi;
    g_tok[b] = fi;
    if (wsamp) out[(size_t)BSZ * TST * VOCAB + (size_t)b * TST + t] = (float)fi;
  }
  __syncthreads();
  const int tok = stok;
  for (int e = tid; e < EDIM; e += 256) {            // embed + split next token
    __half h0, h1;
    split2(emb[(size_t)tok * EDIM + e], h0, h1);
    d_xs[0][b * EDIM + e] = h0;
    d_xs[1][b * EDIM + e] = h1;
  }
}

// ---------------- host orchestration (graph-capturable) ----------------
extern "C" void kernel_launch(void* const* d_in, const int* in_sizes, int n_in,
                              void* d_out, int out_size) {
  const float* emb = (const float*)d_in[0];
  const float* wih = (const float*)d_in[1];
  const float* whh = (const float*)d_in[2];
  const float* bih = (const float*)d_in[3];
  const float* bhh = (const float*)d_in[4];
  const float* o2w = (const float*)d_in[5];
  const float* o2b = (const float*)d_in[6];
  const float* sw  = (const float*)d_in[7];
  const float* sb  = (const float*)d_in[8];
  float* out = (float*)d_out;
  int wsamp = (out_size >= BSZ * TST * VOCAB + BSZ * TST) ? 1 : 0;

  cudaFuncSetAttribute(k_mm, cudaFuncAttributeMaxDynamicSharedMemorySize, SMEM_SZ);

  // 5 setup launches -> first gates k_mm is launch index 5 for ncu -s 5 -c 1
  k_init<<<1024, 256>>>();                                            // 0
  k_embed0<<<256, 256>>>(emb);                                        // 1
  k_splitw<<<1184, 256>>>(wih, 0, (long long)NLAY * GDIM * HDIM);     // 2
  k_splitw<<<1184, 256>>>(whh, 1, (long long)NLAY * GDIM * HDIM);     // 3
  k_splitw<<<592, 256>>>(o2w, 2, (long long)EDIM * HDIM);             // 4

  for (int t = 0; t < TST; t++) {
    // layer 0: x@Wih0 (y<4) + h0@Whh0 (y>=4), 4 K-chunks per slice
    k_mm<<<dim3(GDIM / 256, 8), 256, SMEM_SZ>>>(0, 0, 1, 1, 4, 4, 0, nullptr, nullptr, 0);
    if (t == 0)   // score weight limb0 + norms; needed only before first score
      k_splitsw<<<4000, 256>>>(sw);
    k_act<<<256, 256>>>(bih, bhh, 0);
    // layer 1: h0@Wih1 + h1@Whh1
    k_mm<<<dim3(GDIM / 256, 8), 256, SMEM_SZ>>>(1, 2, 2, 3, 4, 4, 0, nullptr, nullptr, 0);
    k_act<<<256, 256>>>(bih + GDIM, bhh + GDIM, 1);
    // o2emb: h1 @ o2w, 8 split-K slices of 2 chunks
    k_mm<<<dim3(EDIM / 256, 8), 256, SMEM_SZ>>>(2, 4, 2, 4, 2, 8, 1, nullptr, nullptr, 0);
    k_hidred<<<256, 256>>>(o2b);
    // score: hid @ sw, single limb pass, fused bias + store
    k_mm<<<dim3(VOCAB / 256, 1), 256, SMEM_SZ>>>(3, 5, 3, 5, 16, 1, 2, sb, out, t);
    // exact argmax via margin scan + fp32 refinement; next-token embed
    k_refine<<<BSZ, 256>>>(sw, sb, emb, out, t, wsamp);
  }
}